// round 11
// baseline (speedup 1.0000x reference)
#include <cuda_runtime.h>
#include <cstdint>

#define BATCH 4
#define SEQ   8192
#define DM    1024
#define DK    128
#define NB    (BATCH*SEQ)      // 32768 tokens
#define NSLICE 16
#define NPS   (SEQ/NSLICE)     // 512 n per slice
#define PADK  20               // [row][k] layout row stride (16 used + 4 pad)
#define PADW  136              // [k][row] layout row stride (128 used + 8 pad)

// Scratch (device globals -- no dynamic allocation allowed)
__device__ float g_Q [(size_t)NB * DK];                    // 16 MB, tf32-rounded
__device__ float g_K [(size_t)NB * DK];                    // 16 MB, tf32-rounded
__device__ float g_Jr[(size_t)NB * DM];                    // 128 MB, tf32-rounded J
__device__ float g_Mp[(size_t)BATCH * NSLICE * DK * DM];   // 32 MB partials [k][d]
__device__ float g_M [(size_t)BATCH * DM * DK];            // 2 MB, [b][d][k], rounded
__device__ float g_Jn[(size_t)NB * DM];                    // 128 MB (QM*sc + J)

static __device__ __forceinline__ float tf32r(float x) {
    float y; asm("cvt.rna.tf32.f32 %0, %1;" : "=f"(y) : "f"(x)); return y;
}
static __device__ __forceinline__ float4 tf32r4(float4 v) {
    return make_float4(tf32r(v.x), tf32r(v.y), tf32r(v.z), tf32r(v.w));
}
static __device__ __forceinline__ uint32_t s2u(const void* p) {
    uint32_t a;
    asm("{ .reg .u64 t; cvta.to.shared.u64 t, %1; cvt.u32.u64 %0, t; }" : "=r"(a) : "l"(p));
    return a;
}

#define CP16(dst32, src) \
    asm volatile("cp.async.cg.shared.global [%0], [%1], 16;" :: "r"(dst32), "l"(src) : "memory")
#define CPCOMMIT() asm volatile("cp.async.commit_group;" ::: "memory")
#define CPWAIT1()  asm volatile("cp.async.wait_group 1;" ::: "memory")

// 16 x mma.m16n8k8 tf32 on prepared fragments
#define MMA16() \
    _Pragma("unroll") \
    for (int im = 0; im < 4; im++) \
    _Pragma("unroll") \
    for (int jn = 0; jn < 4; jn++) \
        asm volatile( \
            "mma.sync.aligned.m16n8k8.row.col.f32.tf32.tf32.f32 " \
            "{%0,%1,%2,%3}, {%4,%5,%6,%7}, {%8,%9}, {%0,%1,%2,%3};" \
            : "+f"(acc[im][jn][0]), "+f"(acc[im][jn][1]), \
              "+f"(acc[im][jn][2]), "+f"(acc[im][jn][3]) \
            : "r"(afr[im][0]), "r"(afr[im][1]), "r"(afr[im][2]), \
              "r"(afr[im][3]), "r"(bfr[jn][0]), "r"(bfr[jn][1]));

// [out-row][k] layout (PADK): As_[128][PADK], Bs_[128][PADK]
#define MMA_RK(As_, Bs_, ks_) do {                                              \
    uint32_t afr[4][4], bfr[4][2];                                              \
    _Pragma("unroll")                                                           \
    for (int im = 0; im < 4; im++) {                                            \
        afr[im][0] = *(const uint32_t*)&As_[am + im*16    ][(ks_) + tg    ];    \
        afr[im][1] = *(const uint32_t*)&As_[am + im*16 + 8][(ks_) + tg    ];    \
        afr[im][2] = *(const uint32_t*)&As_[am + im*16    ][(ks_) + tg + 4];    \
        afr[im][3] = *(const uint32_t*)&As_[am + im*16 + 8][(ks_) + tg + 4];    \
    }                                                                           \
    _Pragma("unroll")                                                           \
    for (int jn = 0; jn < 4; jn++) {                                            \
        bfr[jn][0] = *(const uint32_t*)&Bs_[bn + jn*8][(ks_) + tg    ];         \
        bfr[jn][1] = *(const uint32_t*)&Bs_[bn + jn*8][(ks_) + tg + 4];         \
    }                                                                           \
    MMA16();                                                                    \
} while (0)

// [k][out-row] layout (PADW): As_[16][PADW], Bs_[16][PADW] (round-8 layout)
#define MMA_KR(As_, Bs_, ks_) do {                                              \
    uint32_t afr[4][4], bfr[4][2];                                              \
    _Pragma("unroll")                                                           \
    for (int im = 0; im < 4; im++) {                                            \
        const uint32_t* p0 = (const uint32_t*)&As_[(ks_) + tg    ][am + im*16]; \
        const uint32_t* p1 = (const uint32_t*)&As_[(ks_) + tg + 4][am + im*16]; \
        afr[im][0] = p0[0]; afr[im][1] = p0[8];                                 \
        afr[im][2] = p1[0]; afr[im][3] = p1[8];                                 \
    }                                                                           \
    _Pragma("unroll")                                                           \
    for (int jn = 0; jn < 4; jn++) {                                            \
        bfr[jn][0] = *(const uint32_t*)&Bs_[(ks_) + tg    ][bn + jn * 8];       \
        bfr[jn][1] = *(const uint32_t*)&Bs_[(ks_) + tg + 4][bn + jn * 8];       \
    }                                                                           \
    MMA16();                                                                    \
} while (0)

#define WARP_IDX()                                                              \
    const int lane = t & 31;                                                    \
    const int w  = t >> 5;                                                      \
    const int wm = w & 1;                                                       \
    const int wn = w >> 1;                                                      \
    const int g  = lane >> 2;                                                   \
    const int tg = lane & 3;                                                    \
    const int am = wm * 64 + g;                                                 \
    const int bn = wn * 32 + g;

// ---------------------------------------------------------------------------
// Kernel 1: Q|K projection. C[m][j] = sum_d J[m][d] * W[j][d]
// blockIdx.y: 0 -> W_Q/g_Q, 1 -> W_K/g_K.  [row][k] layout, BK=16,
// double-buffered LDG+cvt+STS (float4). y==0 also emits tf32-rounded J -> g_Jr.
// Epilogue rounds Q/K so downstream cp.async consumers need no cvt.
// ---------------------------------------------------------------------------
__global__ void __launch_bounds__(256, 2) k_qk(const float* __restrict__ J,
                                               const float* __restrict__ WQ,
                                               const float* __restrict__ WK) {
    __shared__ float As[2][128][PADK];
    __shared__ float Bs[2][128][PADK];
    const int t  = threadIdx.x;
    const int m0 = blockIdx.x * 128;
    const int by = blockIdx.y;
    const float* W = by ? WK : WQ;
    float* OUT     = by ? g_K : g_Q;

    const int row = t >> 1;           // 0..127
    const int q   = t & 1;            // half of a 16-float chunk-row
    WARP_IDX();

    const float* aR = J + (size_t)(m0 + row) * DM + q * 8;
    const float* wR = W + (size_t)row * DM + q * 8;
    float*      jrR = g_Jr + (size_t)(m0 + row) * DM + q * 8;

    {   // prologue -> buf 0
        float4 a0 = tf32r4(*(const float4*)(aR));
        float4 a1 = tf32r4(*(const float4*)(aR + 4));
        float4 b0 = tf32r4(*(const float4*)(wR));
        float4 b1 = tf32r4(*(const float4*)(wR + 4));
        *(float4*)&As[0][row][q * 8]     = a0;
        *(float4*)&As[0][row][q * 8 + 4] = a1;
        *(float4*)&Bs[0][row][q * 8]     = b0;
        *(float4*)&Bs[0][row][q * 8 + 4] = b1;
        if (by == 0) { *(float4*)(jrR) = a0; *(float4*)(jrR + 4) = a1; }
    }
    __syncthreads();

    float acc[4][4][4] = {};
    int buf = 0;
    const int NIT = DM / 16;
    for (int it = 0; it < NIT; it++) {
        const bool hn = (it + 1) < NIT;
        const int nx = buf ^ 1;
        float4 na0, na1;
        if (hn) {
            na0 = *(const float4*)(aR + (it + 1) * 16);
            na1 = *(const float4*)(aR + (it + 1) * 16 + 4);
        }
        MMA_RK(As[buf], Bs[buf], 0);
        float4 nb0, nb1;
        if (hn) {
            na0 = tf32r4(na0); na1 = tf32r4(na1);
            *(float4*)&As[nx][row][q * 8]     = na0;
            *(float4*)&As[nx][row][q * 8 + 4] = na1;
            if (by == 0) {
                *(float4*)(jrR + (it + 1) * 16)     = na0;
                *(float4*)(jrR + (it + 1) * 16 + 4) = na1;
            }
            nb0 = *(const float4*)(wR + (it + 1) * 16);
            nb1 = *(const float4*)(wR + (it + 1) * 16 + 4);
        }
        MMA_RK(As[buf], Bs[buf], 8);
        if (hn) {
            *(float4*)&Bs[nx][row][q * 8]     = tf32r4(nb0);
            *(float4*)&Bs[nx][row][q * 8 + 4] = tf32r4(nb1);
        }
        __syncthreads();
        buf = nx;
    }
#pragma unroll
    for (int im = 0; im < 4; im++)
#pragma unroll
    for (int jn = 0; jn < 4; jn++) {
        const size_t m = (size_t)(m0 + wm * 64 + im * 16 + g);
        const int    c = wn * 32 + jn * 8 + 2 * tg;
        *(float2*)(OUT + m * DK + c) =
            make_float2(tf32r(acc[im][jn][0]), tf32r(acc[im][jn][1]));
        *(float2*)(OUT + (m + 8) * DK + c) =
            make_float2(tf32r(acc[im][jn][2]), tf32r(acc[im][jn][3]));
    }
}

// ---------------------------------------------------------------------------
// Kernel 2: partial M. Mp[b][s][k][d] = sum_{n in slice} K[n][k]*Jr[n][d]
// [k][row] layout (natural: K/Jr rows are contract-major), cp.async 3-stage.
// grid (DM/128, NSLICE, BATCH).
// ---------------------------------------------------------------------------
__global__ void __launch_bounds__(256, 2) k_m() {
    extern __shared__ float sm[];     // 3 stages x (Ks[16][PADW] + Js[16][PADW])
    const int t  = threadIdx.x;
    const int d0 = blockIdx.x * 128;
    const int sl = blockIdx.y;
    const int bb = blockIdx.z;
    WARP_IDX();

    const int nbeg = sl * NPS;
    const float* Kg = g_K  + ((size_t)bb * SEQ + nbeg) * DK;
    const float* Jg = g_Jr + ((size_t)bb * SEQ + nbeg) * DM + d0;

    // chunk map: per tile 512 x 16B chunks; thread handles 2 per tile
    const int r0c = (2 * t)     >> 5, c0c = (2 * t)     & 31;
    const int r1c = (2 * t + 1) >> 5, c1c = (2 * t + 1) & 31;

    float (*KT[3])[PADW], (*JT[3])[PADW];
#pragma unroll
    for (int s = 0; s < 3; s++) {
        KT[s] = (float(*)[PADW])(sm + (size_t)s * 2 * 16 * PADW);
        JT[s] = (float(*)[PADW])(sm + (size_t)s * 2 * 16 * PADW + 16 * PADW);
    }
#define KM_ISSUE(st_, it_) do {                                                 \
    const int nb_ = (it_) * 16;                                                 \
    CP16(s2u(&KT[st_][r0c][c0c * 4]), Kg + (size_t)(nb_ + r0c) * DK + c0c * 4); \
    CP16(s2u(&KT[st_][r1c][c1c * 4]), Kg + (size_t)(nb_ + r1c) * DK + c1c * 4); \
    CP16(s2u(&JT[st_][r0c][c0c * 4]), Jg + (size_t)(nb_ + r0c) * DM + c0c * 4); \
    CP16(s2u(&JT[st_][r1c][c1c * 4]), Jg + (size_t)(nb_ + r1c) * DM + c1c * 4); \
    CPCOMMIT();                                                                 \
} while (0)

    const int NIT = NPS / 16;         // 32
    KM_ISSUE(0, 0);
    KM_ISSUE(1, 1);

    float acc[4][4][4] = {};
    for (int it = 0; it < NIT; it++) {
        CPWAIT1();
        __syncthreads();
        if (it + 2 < NIT) KM_ISSUE((it + 2) % 3, it + 2);
        const int st = it % 3;
        MMA_KR(KT[st], JT[st], 0);
        MMA_KR(KT[st], JT[st], 8);
    }
#undef KM_ISSUE
    float* Mp = g_Mp + (size_t)(bb * NSLICE + sl) * DK * DM;
#pragma unroll
    for (int im = 0; im < 4; im++)
#pragma unroll
    for (int jn = 0; jn < 4; jn++) {
        const int k = wm * 64 + im * 16 + g;
        const int c = d0 + wn * 32 + jn * 8 + 2 * tg;
        *(float2*)(Mp + (size_t)k * DM + c)       = make_float2(acc[im][jn][0], acc[im][jn][1]);
        *(float2*)(Mp + (size_t)(k + 8) * DM + c) = make_float2(acc[im][jn][2], acc[im][jn][3]);
    }
}

// ---------------------------------------------------------------------------
// Kernel 2b: reduce slices + transpose + round: g_M[b][d][k] = tf32r(sum_s Mp)
// grid (DK/32, DM/32, BATCH), block (32,8)
// ---------------------------------------------------------------------------
__global__ void __launch_bounds__(256) k_mred() {
    __shared__ float tl[32][33];
    const int tx = threadIdx.x, ty = threadIdx.y;
    const int k0 = blockIdx.x * 32, d0 = blockIdx.y * 32, b = blockIdx.z;
#pragma unroll
    for (int i = 0; i < 4; i++) {
        float s = 0.f;
#pragma unroll
        for (int sl = 0; sl < NSLICE; sl++)
            s += g_Mp[((size_t)(b * NSLICE + sl) * DK + k0 + ty + i * 8) * DM + d0 + tx];
        tl[ty + i * 8][tx] = tf32r(s);  // tl[k_local][d_local]
    }
    __syncthreads();
#pragma unroll
    for (int i = 0; i < 4; i++)
        g_M[((size_t)b * DM + d0 + ty + i * 8) * DK + k0 + tx] = tl[tx][ty + i * 8];
}

// ---------------------------------------------------------------------------
// Kernel 3: J_new = sc * Q x M + J.  [row][k] layout, cp.async 3-stage.
// A = Q[token][k], B = M[d][k].  grid (NB/128, DM/128).
// ---------------------------------------------------------------------------
__global__ void __launch_bounds__(256, 2) k_out(const float* __restrict__ J) {
    extern __shared__ float sm[];     // 3 stages x (A[128][PADK] + B[128][PADK])
    const int t  = threadIdx.x;
    const int m0 = blockIdx.x * 128;
    const int d0 = blockIdx.y * 128;
    const int bb = m0 / SEQ;
    WARP_IDX();

    const float* Qg = g_Q + (size_t)m0 * DK;
    const float* Mg = g_M + ((size_t)bb * DM + d0) * DK;

    // per tile 512 x 16B chunks (128 rows x 4); thread handles 2 per tile
    const int r0c = (2 * t)     >> 2, c0c = (2 * t)     & 3;
    const int r1c = (2 * t + 1) >> 2, c1c = (2 * t + 1) & 3;

    float (*AT[3])[PADK], (*BT[3])[PADK];
#pragma unroll
    for (int s = 0; s < 3; s++) {
        AT[s] = (float(*)[PADK])(sm + (size_t)s * 2 * 128 * PADK);
        BT[s] = (float(*)[PADK])(sm + (size_t)s * 2 * 128 * PADK + 128 * PADK);
    }
#define KO_ISSUE(st_, it_) do {                                                 \
    const int kb_ = (it_) * 16;                                                 \
    CP16(s2u(&AT[st_][r0c][c0c * 4]), Qg + (size_t)r0c * DK + kb_ + c0c * 4);   \
    CP16(s2u(&AT[st_][r1c][c1c * 4]), Qg + (size_t)r1c * DK + kb_ + c1c * 4);   \
    CP16(s2u(&BT[st_][r0c][c0c * 4]), Mg + (size_t)r0c * DK + kb_ + c0c * 4);   \
    CP16(s2u(&BT[st_][r1c][c1c * 4]), Mg + (size_t)r1c * DK + kb_ + c1c * 4);   \
    CPCOMMIT();                                                                 \
} while (0)

    const int NIT = DK / 16;          // 8
    KO_ISSUE(0, 0);
    KO_ISSUE(1, 1);

    float acc[4][4][4] = {};
    for (int it = 0; it < NIT; it++) {
        CPWAIT1();
        __syncthreads();
        if (it + 2 < NIT) KO_ISSUE((it + 2) % 3, it + 2);
        const int st = it % 3;
        MMA_RK(AT[st], BT[st], 0);
        MMA_RK(AT[st], BT[st], 8);
    }
#undef KO_ISSUE
    const float sc = 0.088388347648318447f;  // 1/sqrt(128)
#pragma unroll
    for (int im = 0; im < 4; im++)
#pragma unroll
    for (int jn = 0; jn < 4; jn++) {
        const size_t m  = (size_t)(m0 + wm * 64 + im * 16 + g);
        const int    dd = d0 + wn * 32 + jn * 8 + 2 * tg;
        float2 j0 = *(const float2*)(J + m * DM + dd);
        float2 j1 = *(const float2*)(J + (m + 8) * DM + dd);
        *(float2*)(g_Jn + m * DM + dd) =
            make_float2(acc[im][jn][0] * sc + j0.x, acc[im][jn][1] * sc + j0.y);
        *(float2*)(g_Jn + (m + 8) * DM + dd) =
            make_float2(acc[im][jn][2] * sc + j1.x, acc[im][jn][3] * sc + j1.y);
    }
}

// ---------------------------------------------------------------------------
// Kernel 4: LayerNorm over last dim (1024). One block (256 thr) per row.
// ---------------------------------------------------------------------------
__global__ void __launch_bounds__(256) k_ln(const float* __restrict__ gamma,
                                            const float* __restrict__ beta,
                                            float* __restrict__ out) {
    __shared__ float sred[8], ssred[8];
    const int t = threadIdx.x;
    const size_t row = blockIdx.x;
    const int dd = t << 2;

    float4 v = *(const float4*)(g_Jn + row * DM + dd);
    float s  = v.x + v.y + v.z + v.w;
    float ss = v.x * v.x + v.y * v.y + v.z * v.z + v.w * v.w;
#pragma unroll
    for (int o = 16; o > 0; o >>= 1) {
        s  += __shfl_xor_sync(0xffffffffu, s,  o);
        ss += __shfl_xor_sync(0xffffffffu, ss, o);
    }
    const int w = t >> 5;
    if ((t & 31) == 0) { sred[w] = s; ssred[w] = ss; }
    __syncthreads();
    s = 0.f; ss = 0.f;
#pragma unroll
    for (int i = 0; i < 8; i++) { s += sred[i]; ss += ssred[i]; }

    const float mean = s * (1.0f / DM);
    const float var  = ss * (1.0f / DM) - mean * mean;
    const float rstd = rsqrtf(var + 1e-5f);

    float4 g = *(const float4*)(gamma + dd);
    float4 b = *(const float4*)(beta + dd);
    float4 o;
    o.x = (v.x - mean) * rstd * g.x + b.x;
    o.y = (v.y - mean) * rstd * g.y + b.y;
    o.z = (v.z - mean) * rstd * g.z + b.z;
    o.w = (v.w - mean) * rstd * g.w + b.w;
    *(float4*)(out + row * DM + dd) = o;
}

// ---------------------------------------------------------------------------
extern "C" void kernel_launch(void* const* d_in, const int* in_sizes, int n_in,
                              void* d_out, int out_size) {
    (void)in_sizes; (void)n_in; (void)out_size;
    const float* J     = (const float*)d_in[0];
    const float* WQ    = (const float*)d_in[1];
    const float* WK    = (const float*)d_in[2];
    const float* gamma = (const float*)d_in[3];
    const float* beta  = (const float*)d_in[4];
    float* out = (float*)d_out;

    const int smem_km = 3 * 2 * 16 * PADW * sizeof(float);    // 52224 B
    const int smem_ko = 3 * 2 * 128 * PADK * sizeof(float);   // 61440 B
    cudaFuncSetAttribute(k_m,   cudaFuncAttributeMaxDynamicSharedMemorySize, smem_km);
    cudaFuncSetAttribute(k_out, cudaFuncAttributeMaxDynamicSharedMemorySize, smem_ko);

    k_qk  <<<dim3(NB / 128, 2), 256>>>(J, WQ, WK);
    k_m   <<<dim3(DM / 128, NSLICE, BATCH), 256, smem_km>>>();
    k_mred<<<dim3(DK / 32, DM / 32, BATCH), dim3(32, 8)>>>();
    k_out <<<dim3(NB / 128, DM / 128), 256, smem_ko>>>(J);
    k_ln  <<<NB, 256>>>(gamma, beta, out);
}